// round 15
// baseline (speedup 1.0000x reference)
#include <cuda_runtime.h>
#include <math.h>
#include <limits.h>

// RewardModel fused kernel (one launch). Only rewards[b, last[b]] are consumed,
// so the [B,S,H]@[H] matvecs are never materialized. One block per batch row:
//   1. front-batched register load of chosen/rejected ids (mask decided by ONE
//      broadcast load: msk[0] != 0 -> start = 0, filter vacuous)
//   2. c_ind/r_ind = first PAD >= start; has_div
//   3. last = min(c_ind, r_ind) - 1  (JAX negative-index wrap)
//   4. one float4 dot-product iteration per thread at row `last`
//   5. deterministic fixed-point atomic loss; last block writes out[0]
//
// Base = best-measured configuration (8.61 us); only delta vs that base is the
// mask-scan elision (-33% trip1 loads, one fewer reduction round).
//
// Inputs (metadata order):
//   0: chosen_ids int32 [B,S]   1: chosen_mask int32 [B,S]
//   2: rejected_ids int32 [B,S] 3: chosen_hidden fp32 [B,S,H]
//   4: rejected_hidden fp32 [B,S,H]  5: v_head_w fp32 [H]
// Output: fp32 [1 + 2B] = [loss, chosen_scores(B), rejected_scores(B)]

#define NT 512
#define MAXK 4            // fast path covers S <= NT*4*MAXK = 8192
#define NW (NT >> 5)

// zero-initialized; the finishing block always resets them for the next replay
__device__ unsigned long long g_acc;   // loss accumulator, 2^32 fixed point
__device__ unsigned int       g_cnt;   // arrival counter

__global__ __launch_bounds__(NT)
void reward_fused_kernel(const int* __restrict__ chosen_ids,
                         const int* __restrict__ chosen_mask,
                         const int* __restrict__ rejected_ids,
                         const float* __restrict__ chosen_hidden,
                         const float* __restrict__ rejected_hidden,
                         const float* __restrict__ v_head_w,
                         float* __restrict__ out,
                         int B, int S, int H) {
    const int b    = blockIdx.x;
    const int tid  = threadIdx.x;
    const int warp = tid >> 5, lane = tid & 31;

    const int* cid = chosen_ids   + (size_t)b * S;
    const int* msk = chosen_mask  + (size_t)b * S;
    const int* rid = rejected_ids + (size_t)b * S;

    __shared__ int   sh_a[NW], sh_b[NW], sh_c[NW];
    __shared__ float sh_fa[NW], sh_fb[NW];
    __shared__ int   sh_bcast;

    const int  K     = S / (NT * 4);
    const bool fastS = ((S & (NT * 4 - 1)) == 0) && (K >= 1) && (K <= MAXK);
    const bool fastH = (H == 1024);

    // ---- preload weights early (independent of the id scan; hides the load) ----
    float4 w4 = make_float4(0.f, 0.f, 0.f, 0.f);
    if (fastH && tid < 256) w4 = *(const float4*)(v_head_w + tid * 4);

    int start, lc = S, lr = S, ldiv = 0;

    if (fastS) {
        // ---- front-batched burst: chosen + rejected only ----
        int4 cv[MAXK], rv[MAXK];
        #pragma unroll
        for (int k = 0; k < MAXK; k++) {
            if (k < K) {
                const int off = k * NT * 4 + tid * 4;
                cv[k] = *(const int4*)(cid + off);
                rv[k] = *(const int4*)(rid + off);
            }
        }
        const int m0 = __ldg(msk);   // ONE broadcast load decides the mask path

        if (m0 != 0) {
            start = 0;               // first nonzero mask is position 0
        } else {
            // rare: full mask scan (correct for arbitrary masks)
            int4 mv[MAXK];
            #pragma unroll
            for (int k = 0; k < MAXK; k++) {
                if (k < K) {
                    const int off = k * NT * 4 + tid * 4;
                    mv[k] = *(const int4*)(msk + off);
                }
            }
            int ls = S;
            #pragma unroll
            for (int k = MAXK - 1; k >= 0; k--) {
                if (k < K) {
                    const int off = k * NT * 4 + tid * 4;
                    if (mv[k].w) ls = off + 3;
                    if (mv[k].z) ls = off + 2;
                    if (mv[k].y) ls = off + 1;
                    if (mv[k].x) ls = off;
                }
            }
            ls = __reduce_min_sync(0xffffffffu, ls);
            if (lane == 0) sh_a[warp] = ls;
            __syncthreads();
            if (warp == 0) {
                int x = (lane < NW) ? sh_a[lane] : INT_MAX;
                x = __reduce_min_sync(0xffffffffu, x);
                if (lane == 0) sh_bcast = (x == S) ? 0 : x;  // all-false -> 0
            }
            __syncthreads();
            start = sh_bcast;
        }

        // first PAD (==0) at pos >= start in each sequence; divergence flag
        #pragma unroll
        for (int k = MAXK - 1; k >= 0; k--) {
            if (k < K) {
                const int off = k * NT * 4 + tid * 4;
                ldiv |= (cv[k].x != rv[k].x) | (cv[k].y != rv[k].y) |
                        (cv[k].z != rv[k].z) | (cv[k].w != rv[k].w);
                if (cv[k].w == 0 && off + 3 >= start) lc = off + 3;
                if (cv[k].z == 0 && off + 2 >= start) lc = off + 2;
                if (cv[k].y == 0 && off + 1 >= start) lc = off + 1;
                if (cv[k].x == 0 && off     >= start) lc = off;
                if (rv[k].w == 0 && off + 3 >= start) lr = off + 3;
                if (rv[k].z == 0 && off + 2 >= start) lr = off + 2;
                if (rv[k].y == 0 && off + 1 >= start) lr = off + 1;
                if (rv[k].x == 0 && off     >= start) lr = off;
            }
        }
    } else {
        // ---- generic fallback ----
        int ls = S;
        for (int s = tid; s < S; s += NT)
            if (msk[s]) { ls = s; break; }   // ascending stride -> first hit is min
        ls = __reduce_min_sync(0xffffffffu, ls);
        if (lane == 0) sh_a[warp] = ls;
        __syncthreads();
        if (warp == 0) {
            int x = (lane < NW) ? sh_a[lane] : INT_MAX;
            x = __reduce_min_sync(0xffffffffu, x);
            if (lane == 0) sh_bcast = (x == S) ? 0 : x;
        }
        __syncthreads();
        start = sh_bcast;

        for (int s = tid; s < S; s += NT) {
            const int c = cid[s], r = rid[s];
            ldiv |= (c != r);
            if (s >= start) {
                if (c == 0 && s < lc) lc = s;
                if (r == 0 && s < lr) lr = s;
            }
        }
    }

    // ---- combined block reduction: lc, lr, div -> last (one round, 2 barriers) ----
    lc   = __reduce_min_sync(0xffffffffu, lc);
    lr   = __reduce_min_sync(0xffffffffu, lr);
    ldiv = (int)__reduce_or_sync(0xffffffffu, (unsigned)ldiv);
    if (lane == 0) { sh_a[warp] = lc; sh_b[warp] = lr; sh_c[warp] = ldiv; }
    __syncthreads();
    if (warp == 0) {
        int xc = (lane < NW) ? sh_a[lane] : INT_MAX;
        int xr = (lane < NW) ? sh_b[lane] : INT_MAX;
        int xd = (lane < NW) ? sh_c[lane] : 0;
        xc = __reduce_min_sync(0xffffffffu, xc);
        xr = __reduce_min_sync(0xffffffffu, xr);
        xd = (int)__reduce_or_sync(0xffffffffu, (unsigned)xd);
        if (lane == 0) {
            const int r_ind = xd ? xr : xc;      // no-div: min(c_ind, S) == c_ind
            int last = min(xc, r_ind) - 1;
            if (last < 0) last += S;             // JAX negative-index wrap
            sh_bcast = last;
        }
    }
    __syncthreads();
    const int last = sh_bcast;

    // ---- dot products at the score position ----
    const float* ch = chosen_hidden   + ((size_t)b * S + last) * H;
    const float* rh = rejected_hidden + ((size_t)b * S + last) * H;

    float ac = 0.f, ar = 0.f;
    if (fastH) {
        if (tid < 256) {                       // one float4 of each row per thread
            const float4 c4 = *(const float4*)(ch + tid * 4);
            const float4 r4 = *(const float4*)(rh + tid * 4);
            ac = c4.x * w4.x + c4.y * w4.y + c4.z * w4.z + c4.w * w4.w;
            ar = r4.x * w4.x + r4.y * w4.y + r4.z * w4.z + r4.w * w4.w;
        }
    } else {
        for (int h = tid; h < H; h += NT) {
            const float w = v_head_w[h];
            ac += ch[h] * w;
            ar += rh[h] * w;
        }
    }

    #pragma unroll
    for (int o = 16; o; o >>= 1) {
        ac += __shfl_down_sync(0xffffffffu, ac, o);
        ar += __shfl_down_sync(0xffffffffu, ar, o);
    }
    if (lane == 0) { sh_fa[warp] = ac; sh_fb[warp] = ar; }
    __syncthreads();

    if (warp == 0) {
        float xc = (lane < NW) ? sh_fa[lane] : 0.f;
        float xr = (lane < NW) ? sh_fb[lane] : 0.f;
        #pragma unroll
        for (int o = 8; o; o >>= 1) {
            xc += __shfl_down_sync(0xffffffffu, xc, o);
            xr += __shfl_down_sync(0xffffffffu, xr, o);
        }
        if (lane == 0) {
            out[1 + b]     = xc;
            out[1 + B + b] = xr;

            // -log_sigmoid(xc - xr) = softplus(xr - xc), numerically stable, >= 0
            const float d  = xc - xr;
            const float lv = fmaxf(-d, 0.f) + log1pf(expf(-fabsf(d)));

            // deterministic fixed-point accumulation (integer adds commute exactly)
            atomicAdd(&g_acc, (unsigned long long)__double2ll_rn((double)lv * 4294967296.0));
            __threadfence();
            const unsigned ticket = atomicAdd(&g_cnt, 1u);
            if (ticket == gridDim.x - 1) {
                const unsigned long long acc64 = atomicAdd(&g_acc, 0ULL);
                out[0] = (float)((double)acc64 * (1.0 / 4294967296.0) / (double)B);
                g_acc = 0ULL;     // reset for the next graph replay
                g_cnt = 0u;
                __threadfence();
            }
        }
    }
}

extern "C" void kernel_launch(void* const* d_in, const int* in_sizes, int n_in,
                              void* d_out, int out_size) {
    const int*   chosen_ids      = (const int*)  d_in[0];
    const int*   chosen_mask     = (const int*)  d_in[1];
    const int*   rejected_ids    = (const int*)  d_in[2];
    const float* chosen_hidden   = (const float*)d_in[3];
    const float* rejected_hidden = (const float*)d_in[4];
    const float* v_head_w        = (const float*)d_in[5];
    float*       out             = (float*)d_out;

    const int B = (out_size - 1) / 2;   // out = [loss, chosen(B), rejected(B)]
    const int S = in_sizes[0] / B;      // chosen_ids is [B,S]
    const int H = in_sizes[5];          // v_head_w is [H]

    reward_fused_kernel<<<B, NT>>>(chosen_ids, chosen_mask, rejected_ids,
                                   chosen_hidden, rejected_hidden, v_head_w,
                                   out, B, S, H);
}

// round 16
// speedup vs baseline: 1.0294x; 1.0294x over previous
#include <cuda_runtime.h>
#include <math.h>
#include <limits.h>

// RewardModel fused kernel (one launch). Only rewards[b, last[b]] are consumed,
// so the [B,S,H]@[H] matvecs are never materialized. One block per batch row:
//   1. front-batched register load of mask/chosen/rejected ids (+ weights)
//   2. start = first nonzero mask; c_ind/r_ind = first PAD >= start; has_div
//   3. last = min(c_ind, r_ind) - 1  (JAX negative-index wrap)
//   4. one float4 dot-product iteration per thread at row `last`
//   5. deterministic fixed-point atomic loss accumulation; last block writes out[0]
//
// FINAL: best-measured configuration across 11 structural variants (8.61 us);
// the problem is launch/ramp-floor dominated at grid=16 — all further in-kernel
// restructuring measured within the +/-0.2 us noise band.
//
// Inputs (metadata order):
//   0: chosen_ids int32 [B,S]   1: chosen_mask int32 [B,S]
//   2: rejected_ids int32 [B,S] 3: chosen_hidden fp32 [B,S,H]
//   4: rejected_hidden fp32 [B,S,H]  5: v_head_w fp32 [H]
// Output: fp32 [1 + 2B] = [loss, chosen_scores(B), rejected_scores(B)]

#define NT 512
#define MAXK 4            // fast path covers S <= NT*4*MAXK = 8192
#define NW (NT >> 5)

// zero-initialized; the finishing block always resets them for the next replay
__device__ unsigned long long g_acc;   // loss accumulator, 2^32 fixed point
__device__ unsigned int       g_cnt;   // arrival counter

__global__ __launch_bounds__(NT)
void reward_fused_kernel(const int* __restrict__ chosen_ids,
                         const int* __restrict__ chosen_mask,
                         const int* __restrict__ rejected_ids,
                         const float* __restrict__ chosen_hidden,
                         const float* __restrict__ rejected_hidden,
                         const float* __restrict__ v_head_w,
                         float* __restrict__ out,
                         int B, int S, int H) {
    const int b    = blockIdx.x;
    const int tid  = threadIdx.x;
    const int warp = tid >> 5, lane = tid & 31;

    const int* cid = chosen_ids   + (size_t)b * S;
    const int* msk = chosen_mask  + (size_t)b * S;
    const int* rid = rejected_ids + (size_t)b * S;

    __shared__ int   sh_a[NW], sh_b[NW], sh_c[NW];
    __shared__ float sh_fa[NW], sh_fb[NW];
    __shared__ int   sh_bcast;

    const int  K     = S / (NT * 4);
    const bool fastS = ((S & (NT * 4 - 1)) == 0) && (K >= 1) && (K <= MAXK);
    const bool fastH = (H == 1024);

    // ---- preload weights early (independent of the id scan; hides the load) ----
    float4 w4 = make_float4(0.f, 0.f, 0.f, 0.f);
    if (fastH && tid < 256) w4 = *(const float4*)(v_head_w + tid * 4);

    int start, lc = S, lr = S, ldiv = 0;

    if (fastS) {
        // ---- one front-batched load burst of all three id arrays ----
        int4 mv[MAXK], cv[MAXK], rv[MAXK];
        #pragma unroll
        for (int k = 0; k < MAXK; k++) {
            if (k < K) {
                const int off = k * NT * 4 + tid * 4;
                mv[k] = *(const int4*)(msk + off);
                cv[k] = *(const int4*)(cid + off);
                rv[k] = *(const int4*)(rid + off);
            }
        }
        // first nonzero mask (descending assignment -> min index wins)
        int ls = S;
        #pragma unroll
        for (int k = MAXK - 1; k >= 0; k--) {
            if (k < K) {
                const int off = k * NT * 4 + tid * 4;
                if (mv[k].w) ls = off + 3;
                if (mv[k].z) ls = off + 2;
                if (mv[k].y) ls = off + 1;
                if (mv[k].x) ls = off;
            }
        }
        ls = __reduce_min_sync(0xffffffffu, ls);
        if (lane == 0) sh_a[warp] = ls;
        __syncthreads();
        if (warp == 0) {
            int x = (lane < NW) ? sh_a[lane] : INT_MAX;
            x = __reduce_min_sync(0xffffffffu, x);
            if (lane == 0) sh_bcast = (x == S) ? 0 : x;   // argmax of all-false -> 0
        }
        __syncthreads();
        start = sh_bcast;

        // first PAD (==0) at pos >= start in each sequence; divergence flag
        #pragma unroll
        for (int k = MAXK - 1; k >= 0; k--) {
            if (k < K) {
                const int off = k * NT * 4 + tid * 4;
                ldiv |= (cv[k].x != rv[k].x) | (cv[k].y != rv[k].y) |
                        (cv[k].z != rv[k].z) | (cv[k].w != rv[k].w);
                if (cv[k].w == 0 && off + 3 >= start) lc = off + 3;
                if (cv[k].z == 0 && off + 2 >= start) lc = off + 2;
                if (cv[k].y == 0 && off + 1 >= start) lc = off + 1;
                if (cv[k].x == 0 && off     >= start) lc = off;
                if (rv[k].w == 0 && off + 3 >= start) lr = off + 3;
                if (rv[k].z == 0 && off + 2 >= start) lr = off + 2;
                if (rv[k].y == 0 && off + 1 >= start) lr = off + 1;
                if (rv[k].x == 0 && off     >= start) lr = off;
            }
        }
    } else {
        // ---- generic fallback ----
        int ls = S;
        for (int s = tid; s < S; s += NT)
            if (msk[s]) { ls = s; break; }   // ascending stride -> first hit is min
        ls = __reduce_min_sync(0xffffffffu, ls);
        if (lane == 0) sh_a[warp] = ls;
        __syncthreads();
        if (warp == 0) {
            int x = (lane < NW) ? sh_a[lane] : INT_MAX;
            x = __reduce_min_sync(0xffffffffu, x);
            if (lane == 0) sh_bcast = (x == S) ? 0 : x;
        }
        __syncthreads();
        start = sh_bcast;

        for (int s = tid; s < S; s += NT) {
            const int c = cid[s], r = rid[s];
            ldiv |= (c != r);
            if (s >= start) {
                if (c == 0 && s < lc) lc = s;
                if (r == 0 && s < lr) lr = s;
            }
        }
    }

    // ---- combined block reduction: lc, lr, div -> last (one round, 2 barriers) ----
    lc   = __reduce_min_sync(0xffffffffu, lc);
    lr   = __reduce_min_sync(0xffffffffu, lr);
    ldiv = (int)__reduce_or_sync(0xffffffffu, (unsigned)ldiv);
    if (lane == 0) { sh_a[warp] = lc; sh_b[warp] = lr; sh_c[warp] = ldiv; }
    __syncthreads();
    if (warp == 0) {
        int xc = (lane < NW) ? sh_a[lane] : INT_MAX;
        int xr = (lane < NW) ? sh_b[lane] : INT_MAX;
        int xd = (lane < NW) ? sh_c[lane] : 0;
        xc = __reduce_min_sync(0xffffffffu, xc);
        xr = __reduce_min_sync(0xffffffffu, xr);
        xd = (int)__reduce_or_sync(0xffffffffu, (unsigned)xd);
        if (lane == 0) {
            const int r_ind = xd ? xr : xc;      // no-div: min(c_ind, S) == c_ind
            int last = min(xc, r_ind) - 1;
            if (last < 0) last += S;             // JAX negative-index wrap
            sh_bcast = last;
        }
    }
    __syncthreads();
    const int last = sh_bcast;

    // ---- dot products at the score position ----
    const float* ch = chosen_hidden   + ((size_t)b * S + last) * H;
    const float* rh = rejected_hidden + ((size_t)b * S + last) * H;

    float ac = 0.f, ar = 0.f;
    if (fastH) {
        if (tid < 256) {                       // one float4 of each row per thread
            const float4 c4 = *(const float4*)(ch + tid * 4);
            const float4 r4 = *(const float4*)(rh + tid * 4);
            ac = c4.x * w4.x + c4.y * w4.y + c4.z * w4.z + c4.w * w4.w;
            ar = r4.x * w4.x + r4.y * w4.y + r4.z * w4.z + r4.w * w4.w;
        }
    } else {
        for (int h = tid; h < H; h += NT) {
            const float w = v_head_w[h];
            ac += ch[h] * w;
            ar += rh[h] * w;
        }
    }

    #pragma unroll
    for (int o = 16; o; o >>= 1) {
        ac += __shfl_down_sync(0xffffffffu, ac, o);
        ar += __shfl_down_sync(0xffffffffu, ar, o);
    }
    if (lane == 0) { sh_fa[warp] = ac; sh_fb[warp] = ar; }
    __syncthreads();

    if (warp == 0) {
        float xc = (lane < NW) ? sh_fa[lane] : 0.f;
        float xr = (lane < NW) ? sh_fb[lane] : 0.f;
        #pragma unroll
        for (int o = 8; o; o >>= 1) {
            xc += __shfl_down_sync(0xffffffffu, xc, o);
            xr += __shfl_down_sync(0xffffffffu, xr, o);
        }
        if (lane == 0) {
            out[1 + b]     = xc;
            out[1 + B + b] = xr;

            // -log_sigmoid(xc - xr) = softplus(xr - xc), numerically stable, >= 0
            const float d  = xc - xr;
            const float lv = fmaxf(-d, 0.f) + log1pf(expf(-fabsf(d)));

            // deterministic fixed-point accumulation (integer adds commute exactly)
            atomicAdd(&g_acc, (unsigned long long)__double2ll_rn((double)lv * 4294967296.0));
            __threadfence();
            const unsigned ticket = atomicAdd(&g_cnt, 1u);
            if (ticket == gridDim.x - 1) {
                const unsigned long long acc64 = atomicAdd(&g_acc, 0ULL);
                out[0] = (float)((double)acc64 * (1.0 / 4294967296.0) / (double)B);
                g_acc = 0ULL;     // reset for the next graph replay
                g_cnt = 0u;
                __threadfence();
            }
        }
    }
}

extern "C" void kernel_launch(void* const* d_in, const int* in_sizes, int n_in,
                              void* d_out, int out_size) {
    const int*   chosen_ids      = (const int*)  d_in[0];
    const int*   chosen_mask     = (const int*)  d_in[1];
    const int*   rejected_ids    = (const int*)  d_in[2];
    const float* chosen_hidden   = (const float*)d_in[3];
    const float* rejected_hidden = (const float*)d_in[4];
    const float* v_head_w        = (const float*)d_in[5];
    float*       out             = (float*)d_out;

    const int B = (out_size - 1) / 2;   // out = [loss, chosen(B), rejected(B)]
    const int S = in_sizes[0] / B;      // chosen_ids is [B,S]
    const int H = in_sizes[5];          // v_head_w is [H]

    reward_fused_kernel<<<B, NT>>>(chosen_ids, chosen_mask, rejected_ids,
                                   chosen_hidden, rejected_hidden, v_head_w,
                                   out, B, S, H);
}

// round 17
// speedup vs baseline: 1.0332x; 1.0037x over previous
#include <cuda_runtime.h>
#include <math.h>
#include <limits.h>

// RewardModel fused kernel (one launch). Only rewards[b, last[b]] are consumed,
// so the [B,S,H]@[H] matvecs are never materialized. One block per batch row:
//   1. front-batched register load of mask/chosen/rejected ids (+ weights)
//   2. start = first nonzero mask; c_ind/r_ind = first PAD >= start; has_div
//   3. last = min(c_ind, r_ind) - 1  (JAX negative-index wrap)
//   4. one float4 dot-product iteration per thread at row `last`
//   5. deterministic fixed-point atomic loss accumulation; last block writes out[0]
//
// FINAL: best-measured configuration (8.61/8.70/8.70 us across three runs of
// this exact source; 11 structural variants all landed within +/-0.2 us).
// The problem is launch/ramp-floor dominated at grid=16: ~4.2 us fixed launch
// overhead + idle-DVFS body with two short L2-hot trips. Algorithmic win vs
// the reference's full matvecs: ~15x (512 MB -> ~1 MB live traffic).
//
// Inputs (metadata order):
//   0: chosen_ids int32 [B,S]   1: chosen_mask int32 [B,S]
//   2: rejected_ids int32 [B,S] 3: chosen_hidden fp32 [B,S,H]
//   4: rejected_hidden fp32 [B,S,H]  5: v_head_w fp32 [H]
// Output: fp32 [1 + 2B] = [loss, chosen_scores(B), rejected_scores(B)]

#define NT 512
#define MAXK 4            // fast path covers S <= NT*4*MAXK = 8192
#define NW (NT >> 5)

// zero-initialized; the finishing block always resets them for the next replay
__device__ unsigned long long g_acc;   // loss accumulator, 2^32 fixed point
__device__ unsigned int       g_cnt;   // arrival counter

__global__ __launch_bounds__(NT)
void reward_fused_kernel(const int* __restrict__ chosen_ids,
                         const int* __restrict__ chosen_mask,
                         const int* __restrict__ rejected_ids,
                         const float* __restrict__ chosen_hidden,
                         const float* __restrict__ rejected_hidden,
                         const float* __restrict__ v_head_w,
                         float* __restrict__ out,
                         int B, int S, int H) {
    const int b    = blockIdx.x;
    const int tid  = threadIdx.x;
    const int warp = tid >> 5, lane = tid & 31;

    const int* cid = chosen_ids   + (size_t)b * S;
    const int* msk = chosen_mask  + (size_t)b * S;
    const int* rid = rejected_ids + (size_t)b * S;

    __shared__ int   sh_a[NW], sh_b[NW], sh_c[NW];
    __shared__ float sh_fa[NW], sh_fb[NW];
    __shared__ int   sh_bcast;

    const int  K     = S / (NT * 4);
    const bool fastS = ((S & (NT * 4 - 1)) == 0) && (K >= 1) && (K <= MAXK);
    const bool fastH = (H == 1024);

    // ---- preload weights early (independent of the id scan; hides the load) ----
    float4 w4 = make_float4(0.f, 0.f, 0.f, 0.f);
    if (fastH && tid < 256) w4 = *(const float4*)(v_head_w + tid * 4);

    int start, lc = S, lr = S, ldiv = 0;

    if (fastS) {
        // ---- one front-batched load burst of all three id arrays ----
        int4 mv[MAXK], cv[MAXK], rv[MAXK];
        #pragma unroll
        for (int k = 0; k < MAXK; k++) {
            if (k < K) {
                const int off = k * NT * 4 + tid * 4;
                mv[k] = *(const int4*)(msk + off);
                cv[k] = *(const int4*)(cid + off);
                rv[k] = *(const int4*)(rid + off);
            }
        }
        // first nonzero mask (descending assignment -> min index wins)
        int ls = S;
        #pragma unroll
        for (int k = MAXK - 1; k >= 0; k--) {
            if (k < K) {
                const int off = k * NT * 4 + tid * 4;
                if (mv[k].w) ls = off + 3;
                if (mv[k].z) ls = off + 2;
                if (mv[k].y) ls = off + 1;
                if (mv[k].x) ls = off;
            }
        }
        ls = __reduce_min_sync(0xffffffffu, ls);
        if (lane == 0) sh_a[warp] = ls;
        __syncthreads();
        if (warp == 0) {
            int x = (lane < NW) ? sh_a[lane] : INT_MAX;
            x = __reduce_min_sync(0xffffffffu, x);
            if (lane == 0) sh_bcast = (x == S) ? 0 : x;   // argmax of all-false -> 0
        }
        __syncthreads();
        start = sh_bcast;

        // first PAD (==0) at pos >= start in each sequence; divergence flag
        #pragma unroll
        for (int k = MAXK - 1; k >= 0; k--) {
            if (k < K) {
                const int off = k * NT * 4 + tid * 4;
                ldiv |= (cv[k].x != rv[k].x) | (cv[k].y != rv[k].y) |
                        (cv[k].z != rv[k].z) | (cv[k].w != rv[k].w);
                if (cv[k].w == 0 && off + 3 >= start) lc = off + 3;
                if (cv[k].z == 0 && off + 2 >= start) lc = off + 2;
                if (cv[k].y == 0 && off + 1 >= start) lc = off + 1;
                if (cv[k].x == 0 && off     >= start) lc = off;
                if (rv[k].w == 0 && off + 3 >= start) lr = off + 3;
                if (rv[k].z == 0 && off + 2 >= start) lr = off + 2;
                if (rv[k].y == 0 && off + 1 >= start) lr = off + 1;
                if (rv[k].x == 0 && off     >= start) lr = off;
            }
        }
    } else {
        // ---- generic fallback ----
        int ls = S;
        for (int s = tid; s < S; s += NT)
            if (msk[s]) { ls = s; break; }   // ascending stride -> first hit is min
        ls = __reduce_min_sync(0xffffffffu, ls);
        if (lane == 0) sh_a[warp] = ls;
        __syncthreads();
        if (warp == 0) {
            int x = (lane < NW) ? sh_a[lane] : INT_MAX;
            x = __reduce_min_sync(0xffffffffu, x);
            if (lane == 0) sh_bcast = (x == S) ? 0 : x;
        }
        __syncthreads();
        start = sh_bcast;

        for (int s = tid; s < S; s += NT) {
            const int c = cid[s], r = rid[s];
            ldiv |= (c != r);
            if (s >= start) {
                if (c == 0 && s < lc) lc = s;
                if (r == 0 && s < lr) lr = s;
            }
        }
    }

    // ---- combined block reduction: lc, lr, div -> last (one round, 2 barriers) ----
    lc   = __reduce_min_sync(0xffffffffu, lc);
    lr   = __reduce_min_sync(0xffffffffu, lr);
    ldiv = (int)__reduce_or_sync(0xffffffffu, (unsigned)ldiv);
    if (lane == 0) { sh_a[warp] = lc; sh_b[warp] = lr; sh_c[warp] = ldiv; }
    __syncthreads();
    if (warp == 0) {
        int xc = (lane < NW) ? sh_a[lane] : INT_MAX;
        int xr = (lane < NW) ? sh_b[lane] : INT_MAX;
        int xd = (lane < NW) ? sh_c[lane] : 0;
        xc = __reduce_min_sync(0xffffffffu, xc);
        xr = __reduce_min_sync(0xffffffffu, xr);
        xd = (int)__reduce_or_sync(0xffffffffu, (unsigned)xd);
        if (lane == 0) {
            const int r_ind = xd ? xr : xc;      // no-div: min(c_ind, S) == c_ind
            int last = min(xc, r_ind) - 1;
            if (last < 0) last += S;             // JAX negative-index wrap
            sh_bcast = last;
        }
    }
    __syncthreads();
    const int last = sh_bcast;

    // ---- dot products at the score position ----
    const float* ch = chosen_hidden   + ((size_t)b * S + last) * H;
    const float* rh = rejected_hidden + ((size_t)b * S + last) * H;

    float ac = 0.f, ar = 0.f;
    if (fastH) {
        if (tid < 256) {                       // one float4 of each row per thread
            const float4 c4 = *(const float4*)(ch + tid * 4);
            const float4 r4 = *(const float4*)(rh + tid * 4);
            ac = c4.x * w4.x + c4.y * w4.y + c4.z * w4.z + c4.w * w4.w;
            ar = r4.x * w4.x + r4.y * w4.y + r4.z * w4.z + r4.w * w4.w;
        }
    } else {
        for (int h = tid; h < H; h += NT) {
            const float w = v_head_w[h];
            ac += ch[h] * w;
            ar += rh[h] * w;
        }
    }

    #pragma unroll
    for (int o = 16; o; o >>= 1) {
        ac += __shfl_down_sync(0xffffffffu, ac, o);
        ar += __shfl_down_sync(0xffffffffu, ar, o);
    }
    if (lane == 0) { sh_fa[warp] = ac; sh_fb[warp] = ar; }
    __syncthreads();

    if (warp == 0) {
        float xc = (lane < NW) ? sh_fa[lane] : 0.f;
        float xr = (lane < NW) ? sh_fb[lane] : 0.f;
        #pragma unroll
        for (int o = 8; o; o >>= 1) {
            xc += __shfl_down_sync(0xffffffffu, xc, o);
            xr += __shfl_down_sync(0xffffffffu, xr, o);
        }
        if (lane == 0) {
            out[1 + b]     = xc;
            out[1 + B + b] = xr;

            // -log_sigmoid(xc - xr) = softplus(xr - xc), numerically stable, >= 0
            const float d  = xc - xr;
            const float lv = fmaxf(-d, 0.f) + log1pf(expf(-fabsf(d)));

            // deterministic fixed-point accumulation (integer adds commute exactly)
            atomicAdd(&g_acc, (unsigned long long)__double2ll_rn((double)lv * 4294967296.0));
            __threadfence();
            const unsigned ticket = atomicAdd(&g_cnt, 1u);
            if (ticket == gridDim.x - 1) {
                const unsigned long long acc64 = atomicAdd(&g_acc, 0ULL);
                out[0] = (float)((double)acc64 * (1.0 / 4294967296.0) / (double)B);
                g_acc = 0ULL;     // reset for the next graph replay
                g_cnt = 0u;
                __threadfence();
            }
        }
    }
}

extern "C" void kernel_launch(void* const* d_in, const int* in_sizes, int n_in,
                              void* d_out, int out_size) {
    const int*   chosen_ids      = (const int*)  d_in[0];
    const int*   chosen_mask     = (const int*)  d_in[1];
    const int*   rejected_ids    = (const int*)  d_in[2];
    const float* chosen_hidden   = (const float*)d_in[3];
    const float* rejected_hidden = (const float*)d_in[4];
    const float* v_head_w        = (const float*)d_in[5];
    float*       out             = (float*)d_out;

    const int B = (out_size - 1) / 2;   // out = [loss, chosen(B), rejected(B)]
    const int S = in_sizes[0] / B;      // chosen_ids is [B,S]
    const int H = in_sizes[5];          // v_head_w is [H]

    reward_fused_kernel<<<B, NT>>>(chosen_ids, chosen_mask, rejected_ids,
                                   chosen_hidden, rejected_hidden, v_head_w,
                                   out, B, S, H);
}